// round 1
// baseline (speedup 1.0000x reference)
#include <cuda_runtime.h>

#define NQ 2048
#define NO 2048
#define LAT 64
#define OSPLIT 2
#define QPW 2
#define NWARPS 4
#define QPB (QPW*NWARPS)      /* 8 queries per block */
#define THREADS (NWARPS*32)   /* 128 */
#define CHUNK 32
#define OHALF (NO/OSPLIT)     /* 1024 */
#define NCHUNK (OHALF/CHUNK)  /* 32 */
#define L2E 1.4426950408889634f
#define NEGBIG (-1e30f)
#define FULLMASK 0xffffffffu

// ---------------- device scratch (no allocations allowed) ----------------
__device__ float4 g_aq4[NQ*LAT/4];      // [q][l4]
__device__ float4 g_bo4[NO*LAT/4];      // interleaved [gchunk][l4][o_in][ (4 floats) ]
__device__ float4 g_v4[NO*LAT/4];       // [o][l4]
__device__ float4 g_pos4[NO];           // (x,y,z,0)
__device__ float  g_pacc[OSPLIT][NQ*LAT];
__device__ float  g_pm[OSPLIT][NQ];
__device__ float  g_ps[OSPLIT][NQ];

// ---------------- prep: separable MLP factors + value projection ----------------
__global__ void prep_kernel(const float* __restrict__ h_obs,
                            const float* __restrict__ pos_obs,
                            const float* __restrict__ pos_query,
                            const float* __restrict__ W1,
                            const float* __restrict__ b1,
                            const float* __restrict__ Wv,
                            const float* __restrict__ bv)
{
    int idx = blockIdx.x * blockDim.x + threadIdx.x;  // NQ*LAT threads (NQ==NO)
    int row = idx >> 6;
    int l   = idx & 63;
    if (row >= NO) return;

    float a = 0.f;
    float b = b1[l];
#pragma unroll
    for (int e = 0; e < 3; e++) {
        float wc = W1[(6+e)*LAT + l];
        a = fmaf(pos_query[row*3 + e], W1[e*LAT + l] + wc, a);
        b = fmaf(pos_obs  [row*3 + e], W1[(3+e)*LAT + l] - wc, b);
    }
    ((float*)g_aq4)[row*LAT + l] = a;

    int ch = row >> 5, oin = row & 31, l4 = l >> 2, li = l & 3;
    ((float*)g_bo4)[(((ch*16) + l4)*32 + oin)*4 + li] = b;

    float v = bv[l];
#pragma unroll 8
    for (int k = 0; k < LAT; k++)
        v = fmaf(h_obs[row*LAT + k], Wv[k*LAT + l], v);
    ((float*)g_v4)[row*LAT + l] = v;

    if (l == 0)
        g_pos4[row] = make_float4(pos_obs[row*3], pos_obs[row*3+1], pos_obs[row*3+2], 0.f);
}

// ---------------- main: fused masked-softmax attention, online ----------------
__global__ __launch_bounds__(THREADS, 8)
void main_kernel(const float* __restrict__ pos_query,
                 const float* __restrict__ W2)
{
    __shared__ float4 s_bo[16][32];    // [l4][o]  (4 latents per float4)
    __shared__ float  s_v[32][64];     // [o][l]
    __shared__ float4 s_pos[32];
    __shared__ float4 s_aq[QPB][16];   // [q][l4]
    __shared__ float4 s_w2[16];
    __shared__ float4 s_qp[QPB];

    const int tid  = threadIdx.x;
    const int warp = tid >> 5;
    const int lane = tid & 31;
    const int qblk = blockIdx.x;        // 0..NQ/QPB-1
    const int split = blockIdx.y;       // 0..OSPLIT-1
    const int obase = split * OHALF;

    // stage per-block constants (once)
    ((float4*)&s_aq[0][0])[tid] = g_aq4[qblk*QPB*16 + tid];   // 128 float4 = 8 q x 64 l
    if (tid < 16) s_w2[tid] = ((const float4*)W2)[tid];
    if (tid < QPB) {
        int q = qblk*QPB + tid;
        s_qp[tid] = make_float4(pos_query[q*3], pos_query[q*3+1], pos_query[q*3+2], 0.f);
    }

    const int qa = warp*QPW, qb = qa + 1;

    float2 accA = make_float2(0.f, 0.f), accB = make_float2(0.f, 0.f);
    float mA = NEGBIG, mB = NEGBIG;
    float sA = 0.f, sB = 0.f;

    // prefetch registers for double-buffering via regs
    float4 pbo[4], pv[4], ppos;
    {
        int gch = split*NCHUNK + 0;
#pragma unroll
        for (int i = 0; i < 4; i++) pbo[i] = g_bo4[gch*512 + i*128 + tid];
#pragma unroll
        for (int i = 0; i < 4; i++) pv[i]  = g_v4[(obase)*16 + i*128 + tid];
        if (tid < 32) ppos = g_pos4[obase + tid];
    }
    __syncthreads();   // s_aq / s_w2 / s_qp visible
    const float4 qpA = s_qp[qa];
    const float4 qpB = s_qp[qb];

    for (int c = 0; c < NCHUNK; c++) {
        // commit prefetched chunk to smem
#pragma unroll
        for (int i = 0; i < 4; i++) ((float4*)&s_bo[0][0])[i*128 + tid] = pbo[i];
#pragma unroll
        for (int i = 0; i < 4; i++) ((float4*)&s_v[0][0])[i*128 + tid]  = pv[i];
        if (tid < 32) s_pos[tid] = ppos;
        __syncthreads();

        if (c + 1 < NCHUNK) {
            int gch = split*NCHUNK + c + 1;
#pragma unroll
            for (int i = 0; i < 4; i++) pbo[i] = g_bo4[gch*512 + i*128 + tid];
#pragma unroll
            for (int i = 0; i < 4; i++) pv[i]  = g_v4[(obase + (c+1)*CHUNK)*16 + i*128 + tid];
            if (tid < 32) ppos = g_pos4[obase + (c+1)*CHUNK + tid];
        }

        // ---- logits: lane owns obs `lane` of this chunk, for 2 queries ----
        float la = 0.f, lb = 0.f;
#pragma unroll
        for (int l4 = 0; l4 < 16; l4++) {
            float4 b  = s_bo[l4][lane];
            float4 a0 = s_aq[qa][l4];
            float4 a1 = s_aq[qb][l4];
            float4 w  = s_w2[l4];
            la = fmaf(fmaxf(a0.x + b.x, 0.f), w.x, la);
            la = fmaf(fmaxf(a0.y + b.y, 0.f), w.y, la);
            la = fmaf(fmaxf(a0.z + b.z, 0.f), w.z, la);
            la = fmaf(fmaxf(a0.w + b.w, 0.f), w.w, la);
            lb = fmaf(fmaxf(a1.x + b.x, 0.f), w.x, lb);
            lb = fmaf(fmaxf(a1.y + b.y, 0.f), w.y, lb);
            lb = fmaf(fmaxf(a1.z + b.z, 0.f), w.z, lb);
            lb = fmaf(fmaxf(a1.w + b.w, 0.f), w.w, lb);
        }

        // ---- radius mask (exact squared distance, matches reference numerics) ----
        float4 po = s_pos[lane];
        float dxa = qpA.x - po.x, dya = qpA.y - po.y, dza = qpA.z - po.z;
        float dxb = qpB.x - po.x, dyb = qpB.y - po.y, dzb = qpB.z - po.z;
        float d2a = fmaf(dxa, dxa, fmaf(dya, dya, dza*dza));
        float d2b = fmaf(dxb, dxb, fmaf(dyb, dyb, dzb*dzb));
        bool va = (d2a <= 0.25f);
        bool vb = (d2b <= 0.25f);
        float ca = va ? la : NEGBIG;
        float cb = vb ? lb : NEGBIG;

        // ---- chunk max (warp butterfly), online-rescale ----
        float cmA = ca, cmB = cb;
#pragma unroll
        for (int off = 16; off > 0; off >>= 1) {
            cmA = fmaxf(cmA, __shfl_xor_sync(FULLMASK, cmA, off));
            cmB = fmaxf(cmB, __shfl_xor_sync(FULLMASK, cmB, off));
        }
        if (cmA > mA) {
            float sc = exp2f((mA - cmA) * L2E);
            accA.x *= sc; accA.y *= sc; sA *= sc; mA = cmA;
        }
        if (cmB > mB) {
            float sc = exp2f((mB - cmB) * L2E);
            accB.x *= sc; accB.y *= sc; sB *= sc; mB = cmB;
        }
        float pA = va ? exp2f((ca - mA) * L2E) : 0.f;
        float pB = vb ? exp2f((cb - mB) * L2E) : 0.f;
        sA += pA; sB += pB;

        // ---- rank-32 update: acc += P * V ----
#pragma unroll
        for (int o = 0; o < 32; o++) {
            float pa = __shfl_sync(FULLMASK, pA, o);
            float pb = __shfl_sync(FULLMASK, pB, o);
            float2 vv = ((const float2*)&s_v[o][0])[lane];
            accA.x = fmaf(pa, vv.x, accA.x);
            accA.y = fmaf(pa, vv.y, accA.y);
            accB.x = fmaf(pb, vv.x, accB.x);
            accB.y = fmaf(pb, vv.y, accB.y);
        }
        __syncthreads();   // compute done before next chunk's smem stores
    }

    // ---- partial epilogue ----
#pragma unroll
    for (int off = 16; off > 0; off >>= 1) {
        sA += __shfl_xor_sync(FULLMASK, sA, off);
        sB += __shfl_xor_sync(FULLMASK, sB, off);
    }
    int gqa = qblk*QPB + qa;
    int gqb = qblk*QPB + qb;
    ((float2*)&g_pacc[split][gqa*LAT])[lane] = accA;
    ((float2*)&g_pacc[split][gqb*LAT])[lane] = accB;
    if (lane == 0) {
        g_pm[split][gqa] = mA; g_ps[split][gqa] = sA;
        g_pm[split][gqb] = mB; g_ps[split][gqb] = sB;
    }
}

// ---------------- combine the OSPLIT partials ----------------
__global__ void combine_kernel(float* __restrict__ out)
{
    int gid = blockIdx.x * blockDim.x + threadIdx.x;   // NQ*32
    int q  = gid >> 5;
    int l2 = gid & 31;
    float m0 = g_pm[0][q], m1 = g_pm[1][q];
    float M  = fmaxf(m0, m1);
    float w0 = exp2f((m0 - M) * L2E);
    float w1 = exp2f((m1 - M) * L2E);
    float denom = g_ps[0][q]*w0 + g_ps[1][q]*w1;
    float inv = 1.f / denom;
    float2 a0 = ((const float2*)&g_pacc[0][q*LAT])[l2];
    float2 a1 = ((const float2*)&g_pacc[1][q*LAT])[l2];
    float2 r;
    r.x = (a0.x*w0 + a1.x*w1) * inv;
    r.y = (a0.y*w0 + a1.y*w1) * inv;
    ((float2*)out)[gid] = r;
}

// ---------------- launch ----------------
extern "C" void kernel_launch(void* const* d_in, const int* in_sizes, int n_in,
                              void* d_out, int out_size)
{
    const float* h_obs     = (const float*)d_in[0];
    // d_in[1] = x_obs (unused by reference)
    const float* pos_obs   = (const float*)d_in[2];
    const float* pos_query = (const float*)d_in[3];
    const float* W1        = (const float*)d_in[4];
    const float* b1        = (const float*)d_in[5];
    const float* W2        = (const float*)d_in[6];
    // d_in[7] = b2 — shift-invariant under softmax, cancels exactly
    const float* Wv        = (const float*)d_in[8];
    const float* bv        = (const float*)d_in[9];

    prep_kernel<<<(NQ*LAT)/256, 256>>>(h_obs, pos_obs, pos_query, W1, b1, Wv, bv);

    dim3 grid(NQ/QPB, OSPLIT);
    main_kernel<<<grid, THREADS>>>(pos_query, W2);

    combine_kernel<<<(NQ*32)/256, 256>>>((float*)d_out);
}

// round 2
// speedup vs baseline: 1.6569x; 1.6569x over previous
#include <cuda_runtime.h>

#define NQ 2048
#define NO 2048
#define LAT 64
#define OSPLIT 8
#define QPW 4
#define NWARPS 4
#define QPB (QPW*NWARPS)      /* 16 queries per block */
#define THREADS (NWARPS*32)   /* 128 */
#define CHUNK 32
#define OPART (NO/OSPLIT)     /* 256 */
#define NCHUNK (OPART/CHUNK)  /* 8 */
#define L2E 1.4426950408889634f
#define NEGBIG (-1e30f)
#define FULLMASK 0xffffffffu

typedef unsigned long long u64;

// ---------------- packed f32x2 helpers ----------------
__device__ __forceinline__ u64 pk(float lo, float hi) {
    u64 r; asm("mov.b64 %0,{%1,%2};" : "=l"(r) : "f"(lo), "f"(hi)); return r;
}
__device__ __forceinline__ void upk(u64 v, float& lo, float& hi) {
    asm("mov.b64 {%0,%1},%2;" : "=f"(lo), "=f"(hi) : "l"(v));
}
__device__ __forceinline__ u64 add2(u64 a, u64 b) {
    u64 d; asm("add.rn.f32x2 %0,%1,%2;" : "=l"(d) : "l"(a), "l"(b)); return d;
}
__device__ __forceinline__ u64 mul2(u64 a, u64 b) {
    u64 d; asm("mul.rn.f32x2 %0,%1,%2;" : "=l"(d) : "l"(a), "l"(b)); return d;
}
__device__ __forceinline__ u64 fma2(u64 a, u64 b, u64 c) {
    u64 d; asm("fma.rn.f32x2 %0,%1,%2,%3;" : "=l"(d) : "l"(a), "l"(b), "l"(c)); return d;
}
__device__ __forceinline__ u64 relu2(u64 y) {
    float lo, hi; upk(y, lo, hi);
    lo = fmaxf(lo, 0.f); hi = fmaxf(hi, 0.f);
    return pk(lo, hi);
}

// ---------------- device scratch ----------------
__device__ float4 g_aq4[NQ*LAT/4];      // [q][l4]
__device__ float4 g_bo4[NO*LAT/4];      // interleaved [gchunk][l4][o_in32][4floats]
__device__ float4 g_v4[NO*LAT/4];       // [o][l4]
__device__ float4 g_pos4[NO];           // (x,y,z,0)
__device__ float  g_pacc[OSPLIT][NQ*LAT];
__device__ float  g_pm[OSPLIT][NQ];
__device__ float  g_ps[OSPLIT][NQ];

// ---------------- prep: separable MLP factors + value projection ----------------
__global__ void prep_kernel(const float* __restrict__ h_obs,
                            const float* __restrict__ pos_obs,
                            const float* __restrict__ pos_query,
                            const float* __restrict__ W1,
                            const float* __restrict__ b1,
                            const float* __restrict__ Wv,
                            const float* __restrict__ bv)
{
    int idx = blockIdx.x * blockDim.x + threadIdx.x;  // NQ*LAT threads (NQ==NO)
    int row = idx >> 6;
    int l   = idx & 63;
    if (row >= NO) return;

    float a = 0.f;
    float b = b1[l];
#pragma unroll
    for (int e = 0; e < 3; e++) {
        float wc = W1[(6+e)*LAT + l];
        a = fmaf(pos_query[row*3 + e], W1[e*LAT + l] + wc, a);
        b = fmaf(pos_obs  [row*3 + e], W1[(3+e)*LAT + l] - wc, b);
    }
    ((float*)g_aq4)[row*LAT + l] = a;

    int ch = row >> 5, oin = row & 31, l4 = l >> 2, li = l & 3;
    ((float*)g_bo4)[(((ch*16) + l4)*32 + oin)*4 + li] = b;

    // v = h_obs @ Wv + bv, float4 h loads + 4 accumulators to break the chain
    const float4* h4 = (const float4*)(h_obs + row*LAT);
    float v0 = bv[l], v1 = 0.f, v2 = 0.f, v3 = 0.f;
#pragma unroll
    for (int k4 = 0; k4 < 16; k4++) {
        float4 h = h4[k4];
        v0 = fmaf(h.x, Wv[(4*k4+0)*LAT + l], v0);
        v1 = fmaf(h.y, Wv[(4*k4+1)*LAT + l], v1);
        v2 = fmaf(h.z, Wv[(4*k4+2)*LAT + l], v2);
        v3 = fmaf(h.w, Wv[(4*k4+3)*LAT + l], v3);
    }
    ((float*)g_v4)[row*LAT + l] = (v0 + v1) + (v2 + v3);

    if (l == 0)
        g_pos4[row] = make_float4(pos_obs[row*3], pos_obs[row*3+1], pos_obs[row*3+2], 0.f);
}

// ---------------- main: fused masked-softmax attention, online ----------------
__global__ __launch_bounds__(THREADS)
void main_kernel(const float* __restrict__ pos_query,
                 const float* __restrict__ W2)
{
    __shared__ float4 s_bo[16*32];       // [l4][o]
    __shared__ float4 s_v4[32*16];       // [o][l4]
    __shared__ float4 s_pos[32];
    __shared__ float4 s_aq[QPB][16];     // [q][l4]
    __shared__ float4 s_w2[16];
    __shared__ float4 s_qp[QPB];
    __shared__ float4 s_p[NWARPS][32][2]; // per warp: {pA,pA,pB,pB},{pC,pC,pD,pD}

    const int tid   = threadIdx.x;
    const int warp  = tid >> 5;
    const int lane  = tid & 31;
    const int qblk  = blockIdx.x;       // 0..NQ/QPB-1
    const int split = blockIdx.y;       // 0..OSPLIT-1
    const int obase = split * OPART;
    const int gch0  = obase / CHUNK;    // first global chunk index

    // stage per-block constants (once)
#pragma unroll
    for (int i = 0; i < 2; i++)
        ((float4*)&s_aq[0][0])[i*THREADS + tid] = g_aq4[qblk*QPB*16 + i*THREADS + tid];
    if (tid < 16) s_w2[tid] = ((const float4*)W2)[tid];
    if (tid < QPB) {
        int q = qblk*QPB + tid;
        s_qp[tid] = make_float4(pos_query[q*3], pos_query[q*3+1], pos_query[q*3+2], 0.f);
    }

    const int q0 = warp*QPW;            // warp's first query (block-local)

    u64   acc[QPW];                     // packed {v[2*lane], v[2*lane+1]} accumulators
    float m[QPW], s[QPW];
#pragma unroll
    for (int q = 0; q < QPW; q++) { acc[q] = 0ULL; m[q] = NEGBIG; s[q] = 0.f; }

    // register prefetch of first chunk
    float4 pbo[4], pv[4], ppos;
    {
#pragma unroll
        for (int i = 0; i < 4; i++) pbo[i] = g_bo4[gch0*512 + i*THREADS + tid];
#pragma unroll
        for (int i = 0; i < 4; i++) pv[i]  = g_v4[obase*16 + i*THREADS + tid];
        if (tid < 32) ppos = g_pos4[obase + tid];
    }
    __syncthreads();   // s_aq / s_w2 / s_qp visible

    float4 qp[QPW];
#pragma unroll
    for (int q = 0; q < QPW; q++) qp[q] = s_qp[q0 + q];

    for (int c = 0; c < NCHUNK; c++) {
        // commit prefetched chunk to smem
#pragma unroll
        for (int i = 0; i < 4; i++) s_bo[i*THREADS + tid] = pbo[i];
#pragma unroll
        for (int i = 0; i < 4; i++) s_v4[i*THREADS + tid] = pv[i];
        if (tid < 32) s_pos[tid] = ppos;
        __syncthreads();

        if (c + 1 < NCHUNK) {
            int gch = gch0 + c + 1;
#pragma unroll
            for (int i = 0; i < 4; i++) pbo[i] = g_bo4[gch*512 + i*THREADS + tid];
#pragma unroll
            for (int i = 0; i < 4; i++) pv[i]  = g_v4[(obase + (c+1)*CHUNK)*16 + i*THREADS + tid];
            if (tid < 32) ppos = g_pos4[obase + (c+1)*CHUNK + tid];
        }

        // ---- logits: lane owns obs `lane`; packed f32x2 over latent pairs ----
        u64 lacc[QPW];
#pragma unroll
        for (int q = 0; q < QPW; q++) lacc[q] = 0ULL;

#pragma unroll
        for (int l4 = 0; l4 < 16; l4++) {
            float4 b4 = s_bo[l4*32 + lane];
            u64 b01 = pk(b4.x, b4.y);
            u64 b23 = pk(b4.z, b4.w);
            float4 w4 = s_w2[l4];
            u64 w01 = pk(w4.x, w4.y);
            u64 w23 = pk(w4.z, w4.w);
#pragma unroll
            for (int q = 0; q < QPW; q++) {
                float4 a4 = s_aq[q0 + q][l4];
                lacc[q] = fma2(relu2(add2(pk(a4.x, a4.y), b01)), w01, lacc[q]);
                lacc[q] = fma2(relu2(add2(pk(a4.z, a4.w), b23)), w23, lacc[q]);
            }
        }

        // ---- radius mask + per-query logit ----
        float4 po = s_pos[lane];
        float lg[QPW]; bool valid[QPW];
#pragma unroll
        for (int q = 0; q < QPW; q++) {
            float lo, hi; upk(lacc[q], lo, hi);
            lg[q] = lo + hi;
            float dx = qp[q].x - po.x, dy = qp[q].y - po.y, dz = qp[q].z - po.z;
            float d2 = fmaf(dx, dx, fmaf(dy, dy, dz*dz));
            valid[q] = (d2 <= 0.25f);
            if (!valid[q]) lg[q] = NEGBIG;
        }

        // ---- chunk max (warp butterfly), online rescale, p ----
        float p[QPW];
#pragma unroll
        for (int q = 0; q < QPW; q++) {
            float cm = lg[q];
#pragma unroll
            for (int off = 16; off > 0; off >>= 1)
                cm = fmaxf(cm, __shfl_xor_sync(FULLMASK, cm, off));
            if (cm > m[q]) {
                float sc = exp2f((m[q] - cm) * L2E);
                u64 sc2 = pk(sc, sc);
                acc[q] = mul2(acc[q], sc2);
                s[q] *= sc;
                m[q] = cm;
            }
            p[q] = valid[q] ? exp2f((lg[q] - m[q]) * L2E) : 0.f;
            s[q] += p[q];
        }

        // publish p duplicated for FFMA2 broadcast loads
        s_p[warp][lane][0] = make_float4(p[0], p[0], p[1], p[1]);
        s_p[warp][lane][1] = make_float4(p[2], p[2], p[3], p[3]);
        __syncwarp();

        // ---- rank-32 update: acc += P * V (packed) ----
#pragma unroll
        for (int o = 0; o < 32; o++) {
            float4 pab = s_p[warp][o][0];
            float4 pcd = s_p[warp][o][1];
            float2 vv = ((const float2*)s_v4)[o*32 + lane];
            u64 vv2 = pk(vv.x, vv.y);
            acc[0] = fma2(pk(pab.x, pab.y), vv2, acc[0]);
            acc[1] = fma2(pk(pab.z, pab.w), vv2, acc[1]);
            acc[2] = fma2(pk(pcd.x, pcd.y), vv2, acc[2]);
            acc[3] = fma2(pk(pcd.z, pcd.w), vv2, acc[3]);
        }
        __syncthreads();   // compute done before next chunk's smem commit
    }

    // ---- partial epilogue ----
#pragma unroll
    for (int q = 0; q < QPW; q++) {
#pragma unroll
        for (int off = 16; off > 0; off >>= 1)
            s[q] += __shfl_xor_sync(FULLMASK, s[q], off);
        int gq = qblk*QPB + q0 + q;
        float lo, hi; upk(acc[q], lo, hi);
        ((float2*)&g_pacc[split][gq*LAT])[lane] = make_float2(lo, hi);
        if (lane == 0) { g_pm[split][gq] = m[q]; g_ps[split][gq] = s[q]; }
    }
}

// ---------------- combine the OSPLIT partials ----------------
__global__ void combine_kernel(float* __restrict__ out)
{
    int gid = blockIdx.x * blockDim.x + threadIdx.x;   // NQ*32
    int q  = gid >> 5;
    int l2 = gid & 31;

    float M = NEGBIG;
#pragma unroll
    for (int sp = 0; sp < OSPLIT; sp++) M = fmaxf(M, g_pm[sp][q]);

    float denom = 0.f;
    float rx = 0.f, ry = 0.f;
#pragma unroll
    for (int sp = 0; sp < OSPLIT; sp++) {
        float w = exp2f((g_pm[sp][q] - M) * L2E);
        denom = fmaf(g_ps[sp][q], w, denom);
        float2 a = ((const float2*)&g_pacc[sp][q*LAT])[l2];
        rx = fmaf(a.x, w, rx);
        ry = fmaf(a.y, w, ry);
    }
    float inv = 1.f / denom;
    ((float2*)out)[gid] = make_float2(rx * inv, ry * inv);
}

// ---------------- launch ----------------
extern "C" void kernel_launch(void* const* d_in, const int* in_sizes, int n_in,
                              void* d_out, int out_size)
{
    const float* h_obs     = (const float*)d_in[0];
    // d_in[1] = x_obs (unused by reference)
    const float* pos_obs   = (const float*)d_in[2];
    const float* pos_query = (const float*)d_in[3];
    const float* W1        = (const float*)d_in[4];
    const float* b1        = (const float*)d_in[5];
    const float* W2        = (const float*)d_in[6];
    // d_in[7] = b2 — shift-invariant under softmax, cancels exactly
    const float* Wv        = (const float*)d_in[8];
    const float* bv        = (const float*)d_in[9];

    prep_kernel<<<(NQ*LAT)/256, 256>>>(h_obs, pos_obs, pos_query, W1, b1, Wv, bv);

    dim3 grid(NQ/QPB, OSPLIT);
    main_kernel<<<grid, THREADS>>>(pos_query, W2);

    combine_kernel<<<(NQ*32)/256, 256>>>((float*)d_out);
}

// round 4
// speedup vs baseline: 1.6733x; 1.0099x over previous
#include <cuda_runtime.h>

#define NQ 2048
#define NO 2048
#define LAT 64
#define OSPLIT 8
#define QPW 4
#define NWARPS 8
#define QPB (QPW*NWARPS)      /* 32 queries per block */
#define THREADS (NWARPS*32)   /* 256 */
#define CHUNK 32
#define OPART (NO/OSPLIT)     /* 256 */
#define NCHUNK (OPART/CHUNK)  /* 8 */
#define L2E 1.4426950408889634f
#define NEGBIG (-1e30f)
#define FULLMASK 0xffffffffu

typedef unsigned long long u64;

// ---------------- packed f32x2 helpers ----------------
__device__ __forceinline__ u64 pk(float lo, float hi) {
    u64 r; asm("mov.b64 %0,{%1,%2};" : "=l"(r) : "f"(lo), "f"(hi)); return r;
}
__device__ __forceinline__ void upk(u64 v, float& lo, float& hi) {
    asm("mov.b64 {%0,%1},%2;" : "=f"(lo), "=f"(hi) : "l"(v));
}
__device__ __forceinline__ u64 add2(u64 a, u64 b) {
    u64 d; asm("add.rn.f32x2 %0,%1,%2;" : "=l"(d) : "l"(a), "l"(b)); return d;
}
__device__ __forceinline__ u64 mul2(u64 a, u64 b) {
    u64 d; asm("mul.rn.f32x2 %0,%1,%2;" : "=l"(d) : "l"(a), "l"(b)); return d;
}
__device__ __forceinline__ u64 fma2(u64 a, u64 b, u64 c) {
    u64 d; asm("fma.rn.f32x2 %0,%1,%2,%3;" : "=l"(d) : "l"(a), "l"(b), "l"(c)); return d;
}
__device__ __forceinline__ u64 relu2(u64 y) {
    float lo, hi; upk(y, lo, hi);
    lo = fmaxf(lo, 0.f); hi = fmaxf(hi, 0.f);
    return pk(lo, hi);
}

// ---------------- cp.async helpers ----------------
__device__ __forceinline__ void cpa16(void* smem, const void* g) {
    unsigned s = (unsigned)__cvta_generic_to_shared(smem);
    asm volatile("cp.async.cg.shared.global [%0], [%1], 16;" :: "r"(s), "l"(g));
}
#define CP_COMMIT() asm volatile("cp.async.commit_group;")
#define CP_WAIT1()  asm volatile("cp.async.wait_group 1;")

// ---------------- device scratch ----------------
__device__ float4 g_aq4[NQ*LAT/4];      // [q][l4]
__device__ float4 g_bo4[NO*LAT/4];      // interleaved [gchunk][l4][o_in32]
__device__ float4 g_v4[NO*LAT/4];       // [o][l4]
__device__ float4 g_pos4[NO];           // (x,y,z,0)
__device__ float  g_pacc[OSPLIT][NQ*LAT];
__device__ float  g_pm[OSPLIT][NQ];
__device__ float  g_ps[OSPLIT][NQ];

// ---------------- prep: heterogeneous grid ----------------
// blocks [0,128):   v = h_obs @ Wv + bv, Wv staged in smem, 16 rows/block
// blocks [128,640): separable MLP factors aq/bo + pos staging
__global__ __launch_bounds__(256)
void prep_kernel(const float* __restrict__ h_obs,
                 const float* __restrict__ pos_obs,
                 const float* __restrict__ pos_query,
                 const float* __restrict__ W1,
                 const float* __restrict__ b1,
                 const float* __restrict__ Wv,
                 const float* __restrict__ bv)
{
    __shared__ float4 s_wv[64*16];   // [k][l4] 16KB
    __shared__ float4 s_bv[16];
    const int tid = threadIdx.x;
    const int blk = blockIdx.x;

    if (blk < 128) {
        // ---- value projection ----
        const float4* wv4 = (const float4*)Wv;
#pragma unroll
        for (int i = 0; i < 4; i++) s_wv[i*256 + tid] = wv4[i*256 + tid];
        if (tid < 16) s_bv[tid] = ((const float4*)bv)[tid];
        __syncthreads();

        const int l4  = tid & 15;
        const int r   = tid >> 4;            // 16 rows per block
        const int row = blk*16 + r;
        const float4* h4 = (const float4*)(h_obs + row*LAT);

        float4 a0 = s_bv[l4];
        float4 a1 = make_float4(0.f,0.f,0.f,0.f);
        float4 a2 = make_float4(0.f,0.f,0.f,0.f);
        float4 a3 = make_float4(0.f,0.f,0.f,0.f);
#pragma unroll
        for (int k4 = 0; k4 < 16; k4++) {
            float4 h = h4[k4];
            float4 w0 = s_wv[(4*k4+0)*16 + l4];
            float4 w1 = s_wv[(4*k4+1)*16 + l4];
            float4 w2 = s_wv[(4*k4+2)*16 + l4];
            float4 w3 = s_wv[(4*k4+3)*16 + l4];
            a0.x = fmaf(h.x, w0.x, a0.x); a0.y = fmaf(h.x, w0.y, a0.y);
            a0.z = fmaf(h.x, w0.z, a0.z); a0.w = fmaf(h.x, w0.w, a0.w);
            a1.x = fmaf(h.y, w1.x, a1.x); a1.y = fmaf(h.y, w1.y, a1.y);
            a1.z = fmaf(h.y, w1.z, a1.z); a1.w = fmaf(h.y, w1.w, a1.w);
            a2.x = fmaf(h.z, w2.x, a2.x); a2.y = fmaf(h.z, w2.y, a2.y);
            a2.z = fmaf(h.z, w2.z, a2.z); a2.w = fmaf(h.z, w2.w, a2.w);
            a3.x = fmaf(h.w, w3.x, a3.x); a3.y = fmaf(h.w, w3.y, a3.y);
            a3.z = fmaf(h.w, w3.z, a3.z); a3.w = fmaf(h.w, w3.w, a3.w);
        }
        float4 v;
        v.x = (a0.x + a1.x) + (a2.x + a3.x);
        v.y = (a0.y + a1.y) + (a2.y + a3.y);
        v.z = (a0.z + a1.z) + (a2.z + a3.z);
        v.w = (a0.w + a1.w) + (a2.w + a3.w);
        g_v4[row*16 + l4] = v;
    } else {
        // ---- separable MLP factors ----
        int idx = (blk - 128)*256 + tid;     // covers NQ*LAT
        int row = idx >> 6;
        int l   = idx & 63;

        float a = 0.f;
        float b = b1[l];
#pragma unroll
        for (int e = 0; e < 3; e++) {
            float wc = W1[(6+e)*LAT + l];
            a = fmaf(pos_query[row*3 + e], W1[e*LAT + l] + wc, a);
            b = fmaf(pos_obs  [row*3 + e], W1[(3+e)*LAT + l] - wc, b);
        }
        ((float*)g_aq4)[row*LAT + l] = a;

        int ch = row >> 5, oin = row & 31, l4i = l >> 2, li = l & 3;
        ((float*)g_bo4)[(((ch*16) + l4i)*32 + oin)*4 + li] = b;

        if (l == 0)
            g_pos4[row] = make_float4(pos_obs[row*3], pos_obs[row*3+1], pos_obs[row*3+2], 0.f);
    }
}

// ---------------- main: fused masked-softmax attention, online ----------------
__global__ __launch_bounds__(THREADS, 3)
void main_kernel(const float* __restrict__ pos_query,
                 const float* __restrict__ W2)
{
    __shared__ float4 s_bo[2][512];      // [buf][l4*32+o]
    __shared__ float4 s_v4[2][512];      // [buf][o*16+l4]
    __shared__ float4 s_pos[2][32];
    __shared__ float4 s_aq[QPB][16];     // [q][l4]
    __shared__ float4 s_w2[16];
    __shared__ float4 s_qp[QPB];
    __shared__ float4 s_p[NWARPS][32][2];

    const int tid   = threadIdx.x;
    const int warp  = tid >> 5;
    const int lane  = tid & 31;
    const int qblk  = blockIdx.x;        // 0..NQ/QPB-1
    const int split = blockIdx.y;        // 0..OSPLIT-1
    const int obase = split * OPART;
    const int gch0  = obase / CHUNK;

    // stage per-block constants
#pragma unroll
    for (int i = 0; i < 2; i++)
        ((float4*)&s_aq[0][0])[i*THREADS + tid] = g_aq4[qblk*QPB*16 + i*THREADS + tid];
    if (tid < 16) s_w2[tid] = ((const float4*)W2)[tid];
    if (tid < QPB) {
        int q = qblk*QPB + tid;
        s_qp[tid] = make_float4(pos_query[q*3], pos_query[q*3+1], pos_query[q*3+2], 0.f);
    }

    // prologue: async-load chunk 0 into buf 0
#pragma unroll
    for (int i = 0; i < 2; i++) {
        cpa16(&s_bo[0][i*THREADS + tid], &g_bo4[gch0*512 + i*THREADS + tid]);
        cpa16(&s_v4[0][i*THREADS + tid], &g_v4[obase*16 + i*THREADS + tid]);
    }
    if (tid < 32) cpa16(&s_pos[0][tid], &g_pos4[obase + tid]);
    CP_COMMIT();

    __syncthreads();   // constants staged

    const int q0 = warp*QPW;
    float4 qp[QPW];
#pragma unroll
    for (int q = 0; q < QPW; q++) qp[q] = s_qp[q0 + q];

    u64   acc[QPW];
    float m[QPW], s[QPW];
#pragma unroll
    for (int q = 0; q < QPW; q++) { acc[q] = 0ULL; m[q] = NEGBIG; s[q] = 0.f; }

    for (int c = 0; c < NCHUNK; c++) {
        const int buf = c & 1;
        // issue next chunk's loads into the other buffer
        if (c + 1 < NCHUNK) {
            const int nb  = buf ^ 1;
            const int gch = gch0 + c + 1;
            const int ob  = obase + (c+1)*CHUNK;
#pragma unroll
            for (int i = 0; i < 2; i++) {
                cpa16(&s_bo[nb][i*THREADS + tid], &g_bo4[gch*512 + i*THREADS + tid]);
                cpa16(&s_v4[nb][i*THREADS + tid], &g_v4[ob*16 + i*THREADS + tid]);
            }
            if (tid < 32) cpa16(&s_pos[nb][tid], &g_pos4[ob + tid]);
        }
        CP_COMMIT();
        CP_WAIT1();        // chunk c's group complete
        __syncthreads();

        // ---- logits: lane owns obs `lane`; packed f32x2 over latent pairs ----
        u64 lacc[QPW];
#pragma unroll
        for (int q = 0; q < QPW; q++) lacc[q] = 0ULL;

#pragma unroll
        for (int l4 = 0; l4 < 16; l4++) {
            float4 b4 = s_bo[buf][l4*32 + lane];
            u64 b01 = pk(b4.x, b4.y);
            u64 b23 = pk(b4.z, b4.w);
            float4 w4 = s_w2[l4];
            u64 w01 = pk(w4.x, w4.y);
            u64 w23 = pk(w4.z, w4.w);
#pragma unroll
            for (int q = 0; q < QPW; q++) {
                float4 a4 = s_aq[q0 + q][l4];
                lacc[q] = fma2(relu2(add2(pk(a4.x, a4.y), b01)), w01, lacc[q]);
                lacc[q] = fma2(relu2(add2(pk(a4.z, a4.w), b23)), w23, lacc[q]);
            }
        }

        // ---- radius mask + per-query logit ----
        float4 po = s_pos[buf][lane];
        float lg[QPW]; bool valid[QPW];
#pragma unroll
        for (int q = 0; q < QPW; q++) {
            float lo, hi; upk(lacc[q], lo, hi);
            lg[q] = lo + hi;
            float dx = qp[q].x - po.x, dy = qp[q].y - po.y, dz = qp[q].z - po.z;
            float d2 = fmaf(dx, dx, fmaf(dy, dy, dz*dz));
            valid[q] = (d2 <= 0.25f);
            if (!valid[q]) lg[q] = NEGBIG;
        }

        // ---- chunk max: 4 independent butterflies (ILP overlaps latency) ----
        float cm[QPW];
#pragma unroll
        for (int q = 0; q < QPW; q++) cm[q] = lg[q];
#pragma unroll
        for (int off = 16; off > 0; off >>= 1) {
#pragma unroll
            for (int q = 0; q < QPW; q++)
                cm[q] = fmaxf(cm[q], __shfl_xor_sync(FULLMASK, cm[q], off));
        }

        // ---- online rescale + p ----
        float p[QPW];
#pragma unroll
        for (int q = 0; q < QPW; q++) {
            if (cm[q] > m[q]) {
                float sc = exp2f((m[q] - cm[q]) * L2E);
                acc[q] = mul2(acc[q], pk(sc, sc));
                s[q] *= sc;
                m[q] = cm[q];
            }
            p[q] = valid[q] ? exp2f((lg[q] - m[q]) * L2E) : 0.f;
            s[q] += p[q];
        }

        // publish p duplicated for f32x2 broadcast loads
        s_p[warp][lane][0] = make_float4(p[0], p[0], p[1], p[1]);
        s_p[warp][lane][1] = make_float4(p[2], p[2], p[3], p[3]);
        __syncwarp();

        // ---- rank-32 update: acc += P * V (packed) ----
#pragma unroll
        for (int o = 0; o < 32; o++) {
            float4 pab = s_p[warp][o][0];
            float4 pcd = s_p[warp][o][1];
            float2 vv = ((const float2*)&s_v4[buf][0])[o*32 + lane];
            u64 vv2 = pk(vv.x, vv.y);
            acc[0] = fma2(pk(pab.x, pab.y), vv2, acc[0]);
            acc[1] = fma2(pk(pab.z, pab.w), vv2, acc[1]);
            acc[2] = fma2(pk(pcd.x, pcd.y), vv2, acc[2]);
            acc[3] = fma2(pk(pcd.z, pcd.w), vv2, acc[3]);
        }
        __syncthreads();   // all warps done with buf before it is refilled
    }

    // ---- partial epilogue ----
#pragma unroll
    for (int q = 0; q < QPW; q++) {
#pragma unroll
        for (int off = 16; off > 0; off >>= 1)
            s[q] += __shfl_xor_sync(FULLMASK, s[q], off);
        int gq = qblk*QPB + q0 + q;
        float lo, hi; upk(acc[q], lo, hi);
        ((float2*)&g_pacc[split][gq*LAT])[lane] = make_float2(lo, hi);
        if (lane == 0) { g_pm[split][gq] = m[q]; g_ps[split][gq] = s[q]; }
    }
}

// ---------------- combine the OSPLIT partials ----------------
__global__ void combine_kernel(float* __restrict__ out)
{
    int gid = blockIdx.x * blockDim.x + threadIdx.x;   // NQ*32
    int q  = gid >> 5;
    int l2 = gid & 31;

    float M = NEGBIG;
#pragma unroll
    for (int sp = 0; sp < OSPLIT; sp++) M = fmaxf(M, g_pm[sp][q]);

    float denom = 0.f;
    float rx = 0.f, ry = 0.f;
#pragma unroll
    for (int sp = 0; sp < OSPLIT; sp++) {
        float w = exp2f((g_pm[sp][q] - M) * L2E);
        denom = fmaf(g_ps[sp][q], w, denom);
        float2 a = ((const float2*)&g_pacc[sp][q*LAT])[l2];
        rx = fmaf(a.x, w, rx);
        ry = fmaf(a.y, w, ry);
    }
    float inv = 1.f / denom;
    ((float2*)out)[gid] = make_float2(rx * inv, ry * inv);
}

// ---------------- launch ----------------
extern "C" void kernel_launch(void* const* d_in, const int* in_sizes, int n_in,
                              void* d_out, int out_size)
{
    const float* h_obs     = (const float*)d_in[0];
    // d_in[1] = x_obs (unused by reference)
    const float* pos_obs   = (const float*)d_in[2];
    const float* pos_query = (const float*)d_in[3];
    const float* W1        = (const float*)d_in[4];
    const float* b1        = (const float*)d_in[5];
    const float* W2        = (const float*)d_in[6];
    // d_in[7] = b2 — cancels in softmax
    const float* Wv        = (const float*)d_in[8];
    const float* bv        = (const float*)d_in[9];

    prep_kernel<<<128 + (NQ*LAT)/256, 256>>>(h_obs, pos_obs, pos_query, W1, b1, Wv, bv);

    dim3 grid(NQ/QPB, OSPLIT);
    main_kernel<<<grid, THREADS>>>(pos_query, W2);

    combine_kernel<<<(NQ*32)/256, 256>>>((float*)d_out);
}

// round 5
// speedup vs baseline: 1.8411x; 1.1003x over previous
#include <cuda_runtime.h>

#define NQ 2048
#define NO 2048
#define LAT 64
#define OSPLIT 16
#define QPW 4
#define NWARPS 8
#define QPB (QPW*NWARPS)      /* 32 queries per block */
#define THREADS (NWARPS*32)   /* 256 */
#define CHUNK 32
#define OPART (NO/OSPLIT)     /* 128 */
#define NCHUNK (OPART/CHUNK)  /* 4 */
#define L2E 1.4426950408889634f
#define NEGBIG (-1e30f)
#define FULLMASK 0xffffffffu

typedef unsigned long long u64;

// ---------------- packed f32x2 helpers ----------------
__device__ __forceinline__ u64 pk(float lo, float hi) {
    u64 r; asm("mov.b64 %0,{%1,%2};" : "=l"(r) : "f"(lo), "f"(hi)); return r;
}
__device__ __forceinline__ void upk(u64 v, float& lo, float& hi) {
    asm("mov.b64 {%0,%1},%2;" : "=f"(lo), "=f"(hi) : "l"(v));
}
__device__ __forceinline__ u64 add2(u64 a, u64 b) {
    u64 d; asm("add.rn.f32x2 %0,%1,%2;" : "=l"(d) : "l"(a), "l"(b)); return d;
}
__device__ __forceinline__ u64 mul2(u64 a, u64 b) {
    u64 d; asm("mul.rn.f32x2 %0,%1,%2;" : "=l"(d) : "l"(a), "l"(b)); return d;
}
__device__ __forceinline__ u64 fma2(u64 a, u64 b, u64 c) {
    u64 d; asm("fma.rn.f32x2 %0,%1,%2,%3;" : "=l"(d) : "l"(a), "l"(b), "l"(c)); return d;
}
__device__ __forceinline__ u64 relu2(u64 y) {
    float lo, hi; upk(y, lo, hi);
    lo = fmaxf(lo, 0.f); hi = fmaxf(hi, 0.f);
    return pk(lo, hi);
}

// ---------------- cp.async helpers ----------------
__device__ __forceinline__ void cpa16(void* smem, const void* g) {
    unsigned s = (unsigned)__cvta_generic_to_shared(smem);
    asm volatile("cp.async.cg.shared.global [%0], [%1], 16;" :: "r"(s), "l"(g));
}
#define CP_COMMIT() asm volatile("cp.async.commit_group;")
#define CP_WAIT1()  asm volatile("cp.async.wait_group 1;")

// ---------------- device scratch ----------------
__device__ float4 g_aq4[NQ*LAT/4];      // [q][l4]
__device__ float4 g_bo4[NO*LAT/4];      // interleaved [gchunk][l4][o_in32]
__device__ float4 g_v4[NO*LAT/4];       // [o][l4]
__device__ float4 g_pos4[NO];           // (x,y,z,0)
__device__ float  g_pacc[OSPLIT][NQ*LAT];
__device__ float  g_pm[OSPLIT][NQ];
__device__ float  g_ps[OSPLIT][NQ];

// ---------------- prep: heterogeneous grid ----------------
// blocks [0,128):   v = h_obs @ Wv + bv, Wv staged in smem, 16 rows/block
// blocks [128,640): separable MLP factors aq/bo + pos staging
__global__ __launch_bounds__(256)
void prep_kernel(const float* __restrict__ h_obs,
                 const float* __restrict__ pos_obs,
                 const float* __restrict__ pos_query,
                 const float* __restrict__ W1,
                 const float* __restrict__ b1,
                 const float* __restrict__ Wv,
                 const float* __restrict__ bv)
{
    __shared__ float4 s_wv[64*16];   // [k][l4] 16KB
    __shared__ float4 s_bv[16];
    const int tid = threadIdx.x;
    const int blk = blockIdx.x;

    if (blk < 128) {
        // ---- value projection ----
        const float4* wv4 = (const float4*)Wv;
#pragma unroll
        for (int i = 0; i < 4; i++) s_wv[i*256 + tid] = wv4[i*256 + tid];
        if (tid < 16) s_bv[tid] = ((const float4*)bv)[tid];
        __syncthreads();

        const int l4  = tid & 15;
        const int r   = tid >> 4;            // 16 rows per block
        const int row = blk*16 + r;
        const float4* h4 = (const float4*)(h_obs + row*LAT);

        float4 a0 = s_bv[l4];
        float4 a1 = make_float4(0.f,0.f,0.f,0.f);
        float4 a2 = make_float4(0.f,0.f,0.f,0.f);
        float4 a3 = make_float4(0.f,0.f,0.f,0.f);
#pragma unroll
        for (int k4 = 0; k4 < 16; k4++) {
            float4 h = h4[k4];
            float4 w0 = s_wv[(4*k4+0)*16 + l4];
            float4 w1 = s_wv[(4*k4+1)*16 + l4];
            float4 w2 = s_wv[(4*k4+2)*16 + l4];
            float4 w3 = s_wv[(4*k4+3)*16 + l4];
            a0.x = fmaf(h.x, w0.x, a0.x); a0.y = fmaf(h.x, w0.y, a0.y);
            a0.z = fmaf(h.x, w0.z, a0.z); a0.w = fmaf(h.x, w0.w, a0.w);
            a1.x = fmaf(h.y, w1.x, a1.x); a1.y = fmaf(h.y, w1.y, a1.y);
            a1.z = fmaf(h.y, w1.z, a1.z); a1.w = fmaf(h.y, w1.w, a1.w);
            a2.x = fmaf(h.z, w2.x, a2.x); a2.y = fmaf(h.z, w2.y, a2.y);
            a2.z = fmaf(h.z, w2.z, a2.z); a2.w = fmaf(h.z, w2.w, a2.w);
            a3.x = fmaf(h.w, w3.x, a3.x); a3.y = fmaf(h.w, w3.y, a3.y);
            a3.z = fmaf(h.w, w3.z, a3.z); a3.w = fmaf(h.w, w3.w, a3.w);
        }
        float4 v;
        v.x = (a0.x + a1.x) + (a2.x + a3.x);
        v.y = (a0.y + a1.y) + (a2.y + a3.y);
        v.z = (a0.z + a1.z) + (a2.z + a3.z);
        v.w = (a0.w + a1.w) + (a2.w + a3.w);
        g_v4[row*16 + l4] = v;
    } else {
        // ---- separable MLP factors ----
        int idx = (blk - 128)*256 + tid;     // covers NQ*LAT
        int row = idx >> 6;
        int l   = idx & 63;

        float a = 0.f;
        float b = b1[l];
#pragma unroll
        for (int e = 0; e < 3; e++) {
            float wc = W1[(6+e)*LAT + l];
            a = fmaf(pos_query[row*3 + e], W1[e*LAT + l] + wc, a);
            b = fmaf(pos_obs  [row*3 + e], W1[(3+e)*LAT + l] - wc, b);
        }
        ((float*)g_aq4)[row*LAT + l] = a;

        int ch = row >> 5, oin = row & 31, l4i = l >> 2, li = l & 3;
        ((float*)g_bo4)[(((ch*16) + l4i)*32 + oin)*4 + li] = b;

        if (l == 0)
            g_pos4[row] = make_float4(pos_obs[row*3], pos_obs[row*3+1], pos_obs[row*3+2], 0.f);
    }
}

// ---------------- main: fused masked-softmax attention, online ----------------
__global__ __launch_bounds__(THREADS, 3)
void main_kernel(const float* __restrict__ pos_query,
                 const float* __restrict__ W2)
{
    __shared__ float4 s_bo[2][512];      // [buf][l4*32+o]
    __shared__ float4 s_v4[2][512];      // [buf][o*16+l4]
    __shared__ float4 s_pos[2][32];
    __shared__ float4 s_aq[QPB][16];     // [q][l4]
    __shared__ float4 s_w2[16];
    __shared__ float4 s_qp[QPB];
    __shared__ float4 s_p[NWARPS][32][2];

    const int tid   = threadIdx.x;
    const int warp  = tid >> 5;
    const int lane  = tid & 31;
    const int qblk  = blockIdx.x;        // 0..NQ/QPB-1
    const int split = blockIdx.y;        // 0..OSPLIT-1
    const int obase = split * OPART;
    const int gch0  = obase / CHUNK;

    // stage per-block constants
#pragma unroll
    for (int i = 0; i < 2; i++)
        ((float4*)&s_aq[0][0])[i*THREADS + tid] = g_aq4[qblk*QPB*16 + i*THREADS + tid];
    if (tid < 16) s_w2[tid] = ((const float4*)W2)[tid];
    if (tid < QPB) {
        int q = qblk*QPB + tid;
        s_qp[tid] = make_float4(pos_query[q*3], pos_query[q*3+1], pos_query[q*3+2], 0.f);
    }

    // prologue: async-load chunk 0 into buf 0
#pragma unroll
    for (int i = 0; i < 2; i++) {
        cpa16(&s_bo[0][i*THREADS + tid], &g_bo4[gch0*512 + i*THREADS + tid]);
        cpa16(&s_v4[0][i*THREADS + tid], &g_v4[obase*16 + i*THREADS + tid]);
    }
    if (tid < 32) cpa16(&s_pos[0][tid], &g_pos4[obase + tid]);
    CP_COMMIT();

    __syncthreads();   // constants staged

    const int q0 = warp*QPW;
    float4 qp[QPW];
#pragma unroll
    for (int q = 0; q < QPW; q++) qp[q] = s_qp[q0 + q];

    u64   acc[QPW];
    float m[QPW], s[QPW];
#pragma unroll
    for (int q = 0; q < QPW; q++) { acc[q] = 0ULL; m[q] = NEGBIG; s[q] = 0.f; }

    for (int c = 0; c < NCHUNK; c++) {
        const int buf = c & 1;
        // issue next chunk's loads into the other buffer
        if (c + 1 < NCHUNK) {
            const int nb  = buf ^ 1;
            const int gch = gch0 + c + 1;
            const int ob  = obase + (c+1)*CHUNK;
#pragma unroll
            for (int i = 0; i < 2; i++) {
                cpa16(&s_bo[nb][i*THREADS + tid], &g_bo4[gch*512 + i*THREADS + tid]);
                cpa16(&s_v4[nb][i*THREADS + tid], &g_v4[ob*16 + i*THREADS + tid]);
            }
            if (tid < 32) cpa16(&s_pos[nb][tid], &g_pos4[ob + tid]);
        }
        CP_COMMIT();
        CP_WAIT1();        // chunk c's group complete
        __syncthreads();

        // ---- logits: lane owns obs `lane`; packed f32x2 over latent pairs ----
        u64 lacc[QPW];
#pragma unroll
        for (int q = 0; q < QPW; q++) lacc[q] = 0ULL;

#pragma unroll
        for (int l4 = 0; l4 < 16; l4++) {
            float4 b4 = s_bo[buf][l4*32 + lane];
            u64 b01 = pk(b4.x, b4.y);
            u64 b23 = pk(b4.z, b4.w);
            float4 w4 = s_w2[l4];
            u64 w01 = pk(w4.x, w4.y);
            u64 w23 = pk(w4.z, w4.w);
#pragma unroll
            for (int q = 0; q < QPW; q++) {
                float4 a4 = s_aq[q0 + q][l4];
                lacc[q] = fma2(relu2(add2(pk(a4.x, a4.y), b01)), w01, lacc[q]);
                lacc[q] = fma2(relu2(add2(pk(a4.z, a4.w), b23)), w23, lacc[q]);
            }
        }

        // ---- radius mask + per-query logit ----
        float4 po = s_pos[buf][lane];
        float lg[QPW]; bool valid[QPW];
#pragma unroll
        for (int q = 0; q < QPW; q++) {
            float lo, hi; upk(lacc[q], lo, hi);
            lg[q] = lo + hi;
            float dx = qp[q].x - po.x, dy = qp[q].y - po.y, dz = qp[q].z - po.z;
            float d2 = fmaf(dx, dx, fmaf(dy, dy, dz*dz));
            valid[q] = (d2 <= 0.25f);
            if (!valid[q]) lg[q] = NEGBIG;
        }

        // ---- chunk max: 4 independent butterflies (ILP overlaps latency) ----
        float cm[QPW];
#pragma unroll
        for (int q = 0; q < QPW; q++) cm[q] = lg[q];
#pragma unroll
        for (int off = 16; off > 0; off >>= 1) {
#pragma unroll
            for (int q = 0; q < QPW; q++)
                cm[q] = fmaxf(cm[q], __shfl_xor_sync(FULLMASK, cm[q], off));
        }

        // ---- online rescale + p ----
        float p[QPW];
#pragma unroll
        for (int q = 0; q < QPW; q++) {
            if (cm[q] > m[q]) {
                float sc = exp2f((m[q] - cm[q]) * L2E);
                acc[q] = mul2(acc[q], pk(sc, sc));
                s[q] *= sc;
                m[q] = cm[q];
            }
            p[q] = valid[q] ? exp2f((lg[q] - m[q]) * L2E) : 0.f;
            s[q] += p[q];
        }

        // publish p duplicated for f32x2 broadcast loads
        s_p[warp][lane][0] = make_float4(p[0], p[0], p[1], p[1]);
        s_p[warp][lane][1] = make_float4(p[2], p[2], p[3], p[3]);
        __syncwarp();

        // ---- rank-32 update: acc += P * V (packed) ----
#pragma unroll
        for (int o = 0; o < 32; o++) {
            float4 pab = s_p[warp][o][0];
            float4 pcd = s_p[warp][o][1];
            float2 vv = ((const float2*)&s_v4[buf][0])[o*32 + lane];
            u64 vv2 = pk(vv.x, vv.y);
            acc[0] = fma2(pk(pab.x, pab.y), vv2, acc[0]);
            acc[1] = fma2(pk(pab.z, pab.w), vv2, acc[1]);
            acc[2] = fma2(pk(pcd.x, pcd.y), vv2, acc[2]);
            acc[3] = fma2(pk(pcd.z, pcd.w), vv2, acc[3]);
        }
        __syncthreads();   // all warps done with buf before it is refilled
    }

    // ---- partial epilogue ----
#pragma unroll
    for (int q = 0; q < QPW; q++) {
#pragma unroll
        for (int off = 16; off > 0; off >>= 1)
            s[q] += __shfl_xor_sync(FULLMASK, s[q], off);
        int gq = qblk*QPB + q0 + q;
        float lo, hi; upk(acc[q], lo, hi);
        ((float2*)&g_pacc[split][gq*LAT])[lane] = make_float2(lo, hi);
        if (lane == 0) { g_pm[split][gq] = m[q]; g_ps[split][gq] = s[q]; }
    }
}

// ---------------- combine the OSPLIT partials ----------------
__global__ void combine_kernel(float* __restrict__ out)
{
    int gid = blockIdx.x * blockDim.x + threadIdx.x;   // NQ*32
    int q  = gid >> 5;
    int l2 = gid & 31;

    float M = NEGBIG;
#pragma unroll
    for (int sp = 0; sp < OSPLIT; sp++) M = fmaxf(M, g_pm[sp][q]);

    float denom = 0.f;
    float rx = 0.f, ry = 0.f;
#pragma unroll
    for (int sp = 0; sp < OSPLIT; sp++) {
        float w = exp2f((g_pm[sp][q] - M) * L2E);
        denom = fmaf(g_ps[sp][q], w, denom);
        float2 a = ((const float2*)&g_pacc[sp][q*LAT])[l2];
        rx = fmaf(a.x, w, rx);
        ry = fmaf(a.y, w, ry);
    }
    float inv = 1.f / denom;
    ((float2*)out)[gid] = make_float2(rx * inv, ry * inv);
}

// ---------------- launch ----------------
extern "C" void kernel_launch(void* const* d_in, const int* in_sizes, int n_in,
                              void* d_out, int out_size)
{
    const float* h_obs     = (const float*)d_in[0];
    // d_in[1] = x_obs (unused by reference)
    const float* pos_obs   = (const float*)d_in[2];
    const float* pos_query = (const float*)d_in[3];
    const float* W1        = (const float*)d_in[4];
    const float* b1        = (const float*)d_in[5];
    const float* W2        = (const float*)d_in[6];
    // d_in[7] = b2 — cancels in softmax
    const float* Wv        = (const float*)d_in[8];
    const float* bv        = (const float*)d_in[9];

    prep_kernel<<<128 + (NQ*LAT)/256, 256>>>(h_obs, pos_obs, pos_query, W1, b1, Wv, bv);

    dim3 grid(NQ/QPB, OSPLIT);
    main_kernel<<<grid, THREADS>>>(pos_query, W2);

    combine_kernel<<<(NQ*32)/256, 256>>>((float*)d_out);
}

// round 6
// speedup vs baseline: 2.1586x; 1.1724x over previous
#include <cuda_runtime.h>

#define NQ 2048
#define NO 2048
#define LAT 64
#define OSPLIT 16
#define QPW 4
#define NWARPS 8
#define QPB (QPW*NWARPS)      /* 32 queries per block */
#define THREADS (NWARPS*32)   /* 256 */
#define OPART (NO/OSPLIT)     /* 128 obs per block */
#define NCHUNK 4              /* 4 chunks of 32 within OPART */
#define L2E 1.4426950408889634f
#define NEGBIG (-1e30f)
#define FULLMASK 0xffffffffu

typedef unsigned long long u64;

// dynamic smem layout (bytes)
#define SV    0        /* float s_v[128*64]            32768 */
#define SBO   32768    /* float4 s_bo[4][16][32]       32768 (aliased by s_p after logits) */
#define SAQ   65536    /* float4 s_aq[32][16]           8192 */
#define SPOS  73728    /* float4 s_pos[128]             2048 */
#define SW2H  75776    /* float4 s_w2h[16]               256 */
#define SOC   76032    /* float  s_oc[128]               512 */
#define SQAC  76544    /* float  s_qac[32]               128 */
#define SMEM_BYTES 76672

// ---------------- packed f32x2 helpers ----------------
__device__ __forceinline__ u64 pk(float lo, float hi) {
    u64 r; asm("mov.b64 %0,{%1,%2};" : "=l"(r) : "f"(lo), "f"(hi)); return r;
}
__device__ __forceinline__ void upk(u64 v, float& lo, float& hi) {
    asm("mov.b64 {%0,%1},%2;" : "=f"(lo), "=f"(hi) : "l"(v));
}
__device__ __forceinline__ u64 add2(u64 a, u64 b) {
    u64 d; asm("add.rn.f32x2 %0,%1,%2;" : "=l"(d) : "l"(a), "l"(b)); return d;
}
__device__ __forceinline__ u64 fma2(u64 a, u64 b, u64 c) {
    u64 d; asm("fma.rn.f32x2 %0,%1,%2,%3;" : "=l"(d) : "l"(a), "l"(b), "l"(c)); return d;
}

// ---------------- cp.async helpers ----------------
__device__ __forceinline__ void cpa16(void* smem, const void* g) {
    unsigned s = (unsigned)__cvta_generic_to_shared(smem);
    asm volatile("cp.async.cg.shared.global [%0], [%1], 16;" :: "r"(s), "l"(g));
}
#define CP_COMMIT() asm volatile("cp.async.commit_group;")
#define CP_WAIT0()  asm volatile("cp.async.wait_group 0;")

// ---------------- device scratch ----------------
__device__ float4 g_aq4[NQ*LAT/4];      // [q][l4]
__device__ float4 g_bo4[NO*LAT/4];      // interleaved [gchunk][l4][o_in32]
__device__ float4 g_v4[NO*LAT/4];       // [o][l4]
__device__ float4 g_pos4[NO];           // (x,y,z,0)
__device__ float  g_qac[NQ];            // sum_l w2h*aq
__device__ float  g_obc[NO];            // sum_l w2h*bo
__device__ float  g_w2h[LAT];           // W2*0.5
__device__ float  g_pacc[OSPLIT][NQ*LAT];
__device__ float  g_pm[OSPLIT][NQ];
__device__ float  g_ps[OSPLIT][NQ];

// ---------------- prep ----------------
// blocks [0,128):   v = h_obs @ Wv + bv (Wv staged in smem)
// blocks [128,640): separable MLP factors aq/bo + per-row w2h-reductions + pos
__global__ __launch_bounds__(256)
void prep_kernel(const float* __restrict__ h_obs,
                 const float* __restrict__ pos_obs,
                 const float* __restrict__ pos_query,
                 const float* __restrict__ W1,
                 const float* __restrict__ b1,
                 const float* __restrict__ W2,
                 const float* __restrict__ Wv,
                 const float* __restrict__ bv)
{
    __shared__ float4 s_wv[64*16];   // 16KB (v branch)
    __shared__ float4 s_bv[16];
    __shared__ float  spa[8], spb[8];
    const int tid = threadIdx.x;
    const int blk = blockIdx.x;

    if (blk < 128) {
        const float4* wv4 = (const float4*)Wv;
#pragma unroll
        for (int i = 0; i < 4; i++) s_wv[i*256 + tid] = wv4[i*256 + tid];
        if (tid < 16) s_bv[tid] = ((const float4*)bv)[tid];
        __syncthreads();

        const int l4  = tid & 15;
        const int r   = tid >> 4;
        const int row = blk*16 + r;
        const float4* h4 = (const float4*)(h_obs + row*LAT);

        float4 a0 = s_bv[l4];
        float4 a1 = make_float4(0.f,0.f,0.f,0.f);
        float4 a2 = make_float4(0.f,0.f,0.f,0.f);
        float4 a3 = make_float4(0.f,0.f,0.f,0.f);
#pragma unroll
        for (int k4 = 0; k4 < 16; k4++) {
            float4 h = h4[k4];
            float4 w0 = s_wv[(4*k4+0)*16 + l4];
            float4 w1 = s_wv[(4*k4+1)*16 + l4];
            float4 w2 = s_wv[(4*k4+2)*16 + l4];
            float4 w3 = s_wv[(4*k4+3)*16 + l4];
            a0.x = fmaf(h.x, w0.x, a0.x); a0.y = fmaf(h.x, w0.y, a0.y);
            a0.z = fmaf(h.x, w0.z, a0.z); a0.w = fmaf(h.x, w0.w, a0.w);
            a1.x = fmaf(h.y, w1.x, a1.x); a1.y = fmaf(h.y, w1.y, a1.y);
            a1.z = fmaf(h.y, w1.z, a1.z); a1.w = fmaf(h.y, w1.w, a1.w);
            a2.x = fmaf(h.z, w2.x, a2.x); a2.y = fmaf(h.z, w2.y, a2.y);
            a2.z = fmaf(h.z, w2.z, a2.z); a2.w = fmaf(h.z, w2.w, a2.w);
            a3.x = fmaf(h.w, w3.x, a3.x); a3.y = fmaf(h.w, w3.y, a3.y);
            a3.z = fmaf(h.w, w3.z, a3.z); a3.w = fmaf(h.w, w3.w, a3.w);
        }
        float4 v;
        v.x = (a0.x + a1.x) + (a2.x + a3.x);
        v.y = (a0.y + a1.y) + (a2.y + a3.y);
        v.z = (a0.z + a1.z) + (a2.z + a3.z);
        v.w = (a0.w + a1.w) + (a2.w + a3.w);
        g_v4[row*16 + l4] = v;
    } else {
        int idx = (blk - 128)*256 + tid;     // covers NQ*LAT
        int row = idx >> 6;
        int l   = idx & 63;

        float a = 0.f;
        float b = b1[l];
#pragma unroll
        for (int e = 0; e < 3; e++) {
            float wc = W1[(6+e)*LAT + l];
            a = fmaf(pos_query[row*3 + e], W1[e*LAT + l] + wc, a);
            b = fmaf(pos_obs  [row*3 + e], W1[(3+e)*LAT + l] - wc, b);
        }
        ((float*)g_aq4)[row*LAT + l] = a;

        int ch = row >> 5, oin = row & 31, l4i = l >> 2, li = l & 3;
        ((float*)g_bo4)[(((ch*16) + l4i)*32 + oin)*4 + li] = b;

        if (l == 0)
            g_pos4[row] = make_float4(pos_obs[row*3], pos_obs[row*3+1], pos_obs[row*3+2], 0.f);

        // w2h-weighted row reductions
        float w2h = 0.5f * W2[l];
        float ta = w2h * a, tb = w2h * b;
#pragma unroll
        for (int off = 16; off > 0; off >>= 1) {
            ta += __shfl_xor_sync(FULLMASK, ta, off);
            tb += __shfl_xor_sync(FULLMASK, tb, off);
        }
        int wl = tid >> 5;
        if ((tid & 31) == 0) { spa[wl] = ta; spb[wl] = tb; }
        __syncthreads();
        if ((tid & 63) == 0) {
            g_qac[row] = spa[wl] + spa[wl+1];
            g_obc[row] = spb[wl] + spb[wl+1];
        }
        if (blk == 128 && tid < 64)
            g_w2h[tid] = 0.5f * W2[tid];
    }
}

// ---------------- main: fused masked-softmax attention ----------------
__global__ __launch_bounds__(THREADS, 3)
void main_kernel(const float* __restrict__ pos_query)
{
    extern __shared__ char sm[];
    const int tid   = threadIdx.x;
    const int warp  = tid >> 5;
    const int lane  = tid & 31;
    const int qblk  = blockIdx.x;        // 0..63
    const int split = blockIdx.y;        // 0..15
    const int obase = split * OPART;
    const int gch0  = obase / 32;

    // ---- prologue: one-shot async staging of all tiles ----
    {
        float4* sv = (float4*)(sm + SV);
        float4* sb = (float4*)(sm + SBO);
        const float4* gv = g_v4  + obase*16;
        const float4* gb = g_bo4 + gch0*512;
#pragma unroll
        for (int i = 0; i < 8; i++) {
            cpa16(&sv[i*THREADS + tid], &gv[i*THREADS + tid]);
            cpa16(&sb[i*THREADS + tid], &gb[i*THREADS + tid]);
        }
        float4* sa = (float4*)(sm + SAQ);
        const float4* ga = g_aq4 + qblk*QPB*16;
#pragma unroll
        for (int i = 0; i < 2; i++)
            cpa16(&sa[i*THREADS + tid], &ga[i*THREADS + tid]);
        if (tid < 128) cpa16(&((float4*)(sm + SPOS))[tid], &g_pos4[obase + tid]);
        if (tid < 16)  cpa16(&((float4*)(sm + SW2H))[tid], &((const float4*)g_w2h)[tid]);
        if (tid < 32)  cpa16((float*)(sm + SOC) + tid*4, &g_obc[obase + tid*4]);
        if (tid < 8)   cpa16((float*)(sm + SQAC) + tid*4, &g_qac[qblk*QPB + tid*4]);
        CP_COMMIT();
    }

    // per-warp query constants (broadcast global loads, L1/L2-resident)
    const int q0  = warp*QPW;
    const int gq0 = qblk*QPB + q0;
    float qpx[QPW], qpy[QPW], qpz[QPW];
#pragma unroll
    for (int q = 0; q < QPW; q++) {
        qpx[q] = pos_query[(gq0+q)*3 + 0];
        qpy[q] = pos_query[(gq0+q)*3 + 1];
        qpz[q] = pos_query[(gq0+q)*3 + 2];
    }

    CP_WAIT0();
    __syncthreads();

    // ---- logits for all 128 obs: lacc[q][c] ----
    float lacc[QPW*NCHUNK];
#pragma unroll
    for (int i = 0; i < QPW*NCHUNK; i++) lacc[i] = 0.f;

    const u64* aqp  = (const u64*)(sm + SAQ);
    const u64* bop  = (const u64*)(sm + SBO);
    const float4* w2h4 = (const float4*)(sm + SW2H);

#pragma unroll 1
    for (int l4 = 0; l4 < 16; l4++) {
        float4 w = w2h4[l4];
        u64 a01[QPW], a23[QPW];
#pragma unroll
        for (int q = 0; q < QPW; q++) {
            a01[q] = aqp[((q0+q)*16 + l4)*2 + 0];
            a23[q] = aqp[((q0+q)*16 + l4)*2 + 1];
        }
#pragma unroll
        for (int c = 0; c < NCHUNK; c++) {
            u64 b01 = bop[((c*16 + l4)*32 + lane)*2 + 0];
            u64 b23 = bop[((c*16 + l4)*32 + lane)*2 + 1];
#pragma unroll
            for (int q = 0; q < QPW; q++) {
                float f0, f1, f2, f3;
                upk(add2(a01[q], b01), f0, f1);
                upk(add2(a23[q], b23), f2, f3);
                float t = lacc[q*NCHUNK + c];
                t = fmaf(w.x, fabsf(f0), t);
                t = fmaf(w.y, fabsf(f1), t);
                t = fmaf(w.z, fabsf(f2), t);
                t = fmaf(w.w, fabsf(f3), t);
                lacc[q*NCHUNK + c] = t;
            }
        }
    }

    // ---- assemble logits + radius mask ----
    const float* s_oc  = (const float*)(sm + SOC);
    const float* s_qac = (const float*)(sm + SQAC);
    const float4* s_pos = (const float4*)(sm + SPOS);

    float lg[QPW*NCHUNK];
    bool  vld[QPW*NCHUNK];
#pragma unroll
    for (int c = 0; c < NCHUNK; c++) {
        float4 po = s_pos[c*32 + lane];
        float oc  = s_oc[c*32 + lane];
#pragma unroll
        for (int q = 0; q < QPW; q++) {
            float dx = qpx[q] - po.x, dy = qpy[q] - po.y, dz = qpz[q] - po.z;
            float d2 = fmaf(dx, dx, fmaf(dy, dy, dz*dz));
            bool v = (d2 <= 0.25f);
            vld[q*NCHUNK + c] = v;
            float l = s_qac[q0+q] + oc + lacc[q*NCHUNK + c];
            lg[q*NCHUNK + c] = v ? l : NEGBIG;
        }
    }

    // ---- single-pass softmax stats ----
    float m[QPW], s[QPW], p[QPW*NCHUNK];
#pragma unroll
    for (int q = 0; q < QPW; q++) {
        float cm = fmaxf(fmaxf(lg[q*NCHUNK], lg[q*NCHUNK+1]),
                         fmaxf(lg[q*NCHUNK+2], lg[q*NCHUNK+3]));
#pragma unroll
        for (int off = 16; off > 0; off >>= 1)
            cm = fmaxf(cm, __shfl_xor_sync(FULLMASK, cm, off));
        m[q] = cm;
        float sl = 0.f;
#pragma unroll
        for (int c = 0; c < NCHUNK; c++) {
            float pe = vld[q*NCHUNK+c] ? exp2f((lg[q*NCHUNK+c] - cm) * L2E) : 0.f;
            p[q*NCHUNK+c] = pe;
            sl += pe;
        }
        s[q] = sl;
    }

    __syncthreads();   // all b-reads done: SBO region now reusable as s_p

    // ---- P*V: per-chunk rank-32 updates (warp-private s_p) ----
    float4* s_p4 = (float4*)(sm + SBO + warp*1024);
    const u64* s_pu = (const u64*)(sm + SBO + warp*1024);
    u64 acc[QPW];
#pragma unroll
    for (int q = 0; q < QPW; q++) acc[q] = 0ULL;

#pragma unroll 1
    for (int c = 0; c < NCHUNK; c++) {
        s_p4[lane*2 + 0] = make_float4(p[0*NCHUNK+c], p[0*NCHUNK+c], p[1*NCHUNK+c], p[1*NCHUNK+c]);
        s_p4[lane*2 + 1] = make_float4(p[2*NCHUNK+c], p[2*NCHUNK+c], p[3*NCHUNK+c], p[3*NCHUNK+c]);
        __syncwarp();
        const u64* vvb = (const u64*)(sm + SV) + c*32*32 + lane;
#pragma unroll
        for (int o = 0; o < 32; o++) {
            u64 vv2 = vvb[o*32];
            acc[0] = fma2(s_pu[o*4 + 0], vv2, acc[0]);
            acc[1] = fma2(s_pu[o*4 + 1], vv2, acc[1]);
            acc[2] = fma2(s_pu[o*4 + 2], vv2, acc[2]);
            acc[3] = fma2(s_pu[o*4 + 3], vv2, acc[3]);
        }
        __syncwarp();
    }

    // ---- partial epilogue ----
#pragma unroll
    for (int q = 0; q < QPW; q++) {
        float sl = s[q];
#pragma unroll
        for (int off = 16; off > 0; off >>= 1)
            sl += __shfl_xor_sync(FULLMASK, sl, off);
        int gq = gq0 + q;
        float lo, hi; upk(acc[q], lo, hi);
        ((float2*)&g_pacc[split][gq*LAT])[lane] = make_float2(lo, hi);
        if (lane == 0) { g_pm[split][gq] = m[q]; g_ps[split][gq] = sl; }
    }
}

// ---------------- combine the OSPLIT partials ----------------
__global__ void combine_kernel(float* __restrict__ out)
{
    int gid = blockIdx.x * blockDim.x + threadIdx.x;   // NQ*32
    int q  = gid >> 5;
    int l2 = gid & 31;

    float M = NEGBIG;
#pragma unroll
    for (int sp = 0; sp < OSPLIT; sp++) M = fmaxf(M, g_pm[sp][q]);

    float denom = 0.f;
    float rx = 0.f, ry = 0.f;
#pragma unroll
    for (int sp = 0; sp < OSPLIT; sp++) {
        float w = exp2f((g_pm[sp][q] - M) * L2E);
        denom = fmaf(g_ps[sp][q], w, denom);
        float2 a = ((const float2*)&g_pacc[sp][q*LAT])[l2];
        rx = fmaf(a.x, w, rx);
        ry = fmaf(a.y, w, ry);
    }
    float inv = 1.f / denom;
    ((float2*)out)[gid] = make_float2(rx * inv, ry * inv);
}

// ---------------- launch ----------------
extern "C" void kernel_launch(void* const* d_in, const int* in_sizes, int n_in,
                              void* d_out, int out_size)
{
    const float* h_obs     = (const float*)d_in[0];
    // d_in[1] = x_obs (unused by reference)
    const float* pos_obs   = (const float*)d_in[2];
    const float* pos_query = (const float*)d_in[3];
    const float* W1        = (const float*)d_in[4];
    const float* b1        = (const float*)d_in[5];
    const float* W2        = (const float*)d_in[6];
    // d_in[7] = b2 — cancels in softmax
    const float* Wv        = (const float*)d_in[8];
    const float* bv        = (const float*)d_in[9];

    cudaFuncSetAttribute(main_kernel,
                         cudaFuncAttributeMaxDynamicSharedMemorySize, SMEM_BYTES);

    prep_kernel<<<128 + (NQ*LAT)/256, 256>>>(h_obs, pos_obs, pos_query, W1, b1, W2, Wv, bv);

    dim3 grid(NQ/QPB, OSPLIT);
    main_kernel<<<grid, THREADS, SMEM_BYTES>>>(pos_query);

    combine_kernel<<<(NQ*32)/256, 256>>>((float*)d_out);
}